// round 1
// baseline (speedup 1.0000x reference)
#include <cuda_runtime.h>
#include <cuda_bf16.h>

// GaussianModel preprocess:
//   opacity = sigmoid(opacity_logit)
//   scale   = exp(scale_log)
//   rgb     = sigmoid(C0*sh0 - C1*y*sh1 + C1*z*sh2 - C1*x*sh3)
//   R       = quat_to_rot(normalize(q))
//   M       = R * scale (column-wise)
//   cov3d   = M @ M^T
// Output layout (fp32): [xyz (N*3) | cov3d (N*9) | rgb (N*3) | opacity (N*1)] = 16N

#define C0 0.28209479177387814f
#define C1 0.4886025119029199f

__device__ __forceinline__ float sigmoidf_(float v) {
    return 1.0f / (1.0f + __expf(-v));
}

__global__ __launch_bounds__(256)
void gaussian_kernel(const float* __restrict__ view_dirs,
                     const float* __restrict__ xyz,
                     const float* __restrict__ scale_log,
                     const float* __restrict__ rot_quat,   // N x 4, float4-aligned
                     const float* __restrict__ opacity_logit,
                     const float* __restrict__ sh_coeffs,  // N x 12, 3x float4 per row
                     float* __restrict__ out,
                     int n)
{
    int i = blockIdx.x * blockDim.x + threadIdx.x;
    int stride = gridDim.x * blockDim.x;

    float* out_xyz = out;
    float* out_cov = out + (size_t)n * 3;
    float* out_rgb = out + (size_t)n * 12;   // 3N + 9N
    float* out_opa = out + (size_t)n * 15;

    const float4* quat4 = reinterpret_cast<const float4*>(rot_quat);
    const float4* sh4   = reinterpret_cast<const float4*>(sh_coeffs);

    for (; i < n; i += stride) {
        // ---- passthrough xyz ----
        float px = xyz[i * 3 + 0];
        float py = xyz[i * 3 + 1];
        float pz = xyz[i * 3 + 2];

        // ---- opacity ----
        float opa = sigmoidf_(opacity_logit[i]);

        // ---- SH eval -> rgb ----
        float dx = view_dirs[i * 3 + 0];
        float dy = view_dirs[i * 3 + 1];
        float dz = view_dirs[i * 3 + 2];

        float4 shr = sh4[i * 3 + 0];  // channel R: c0..c3
        float4 shg = sh4[i * 3 + 1];
        float4 shb = sh4[i * 3 + 2];

        float r = sigmoidf_(C0 * shr.x - C1 * dy * shr.y + C1 * dz * shr.z - C1 * dx * shr.w);
        float g = sigmoidf_(C0 * shg.x - C1 * dy * shg.y + C1 * dz * shg.z - C1 * dx * shg.w);
        float b = sigmoidf_(C0 * shb.x - C1 * dy * shb.y + C1 * dz * shb.z - C1 * dx * shb.w);

        // ---- scale ----
        float s0 = __expf(scale_log[i * 3 + 0]);
        float s1 = __expf(scale_log[i * 3 + 1]);
        float s2 = __expf(scale_log[i * 3 + 2]);

        // ---- rotation from quaternion ----
        float4 q = quat4[i];
        float nrm = sqrtf(q.x * q.x + q.y * q.y + q.z * q.z + q.w * q.w);
        float inv = 1.0f / fmaxf(nrm, 1e-12f);
        float qr = q.x * inv, qx = q.y * inv, qy = q.z * inv, qz = q.w * inv;

        float R00 = 1.0f - 2.0f * (qy * qy + qz * qz);
        float R01 = 2.0f * (qx * qy - qr * qz);
        float R02 = 2.0f * (qx * qz + qr * qy);
        float R10 = 2.0f * (qx * qy + qr * qz);
        float R11 = 1.0f - 2.0f * (qx * qx + qz * qz);
        float R12 = 2.0f * (qy * qz - qr * qx);
        float R20 = 2.0f * (qx * qz - qr * qy);
        float R21 = 2.0f * (qy * qz + qr * qx);
        float R22 = 1.0f - 2.0f * (qx * qx + qy * qy);

        // M = R * scale (per-column scale)
        float M00 = R00 * s0, M01 = R01 * s1, M02 = R02 * s2;
        float M10 = R10 * s0, M11 = R11 * s1, M12 = R12 * s2;
        float M20 = R20 * s0, M21 = R21 * s1, M22 = R22 * s2;

        // cov = M * M^T
        float c00 = M00 * M00 + M01 * M01 + M02 * M02;
        float c01 = M00 * M10 + M01 * M11 + M02 * M12;
        float c02 = M00 * M20 + M01 * M21 + M02 * M22;
        float c11 = M10 * M10 + M11 * M11 + M12 * M12;
        float c12 = M10 * M20 + M11 * M21 + M12 * M22;
        float c22 = M20 * M20 + M21 * M21 + M22 * M22;

        // ---- stores ----
        out_xyz[i * 3 + 0] = px;
        out_xyz[i * 3 + 1] = py;
        out_xyz[i * 3 + 2] = pz;

        float* cv = out_cov + (size_t)i * 9;
        cv[0] = c00; cv[1] = c01; cv[2] = c02;
        cv[3] = c01; cv[4] = c11; cv[5] = c12;
        cv[6] = c02; cv[7] = c12; cv[8] = c22;

        out_rgb[i * 3 + 0] = r;
        out_rgb[i * 3 + 1] = g;
        out_rgb[i * 3 + 2] = b;

        out_opa[i] = opa;
    }
}

extern "C" void kernel_launch(void* const* d_in, const int* in_sizes, int n_in,
                              void* d_out, int out_size) {
    const float* view_dirs     = (const float*)d_in[0];
    const float* xyz           = (const float*)d_in[1];
    const float* scale_log     = (const float*)d_in[2];
    const float* rot_quat      = (const float*)d_in[3];
    const float* opacity_logit = (const float*)d_in[4];
    const float* sh_coeffs     = (const float*)d_in[5];
    float* out = (float*)d_out;

    int n = in_sizes[1] / 3;  // xyz has N*3 elements

    int threads = 256;
    int blocks = (n + threads - 1) / threads;
    if (blocks > 148 * 16) blocks = 148 * 16;  // grid-stride cap, full-chip waves
    gaussian_kernel<<<blocks, threads>>>(view_dirs, xyz, scale_log, rot_quat,
                                         opacity_logit, sh_coeffs, out, n);
}

// round 2
// speedup vs baseline: 1.3193x; 1.3193x over previous
#include <cuda_runtime.h>
#include <cuda_bf16.h>

// GaussianModel preprocess, smem-staged fully-coalesced version.
// Output layout (fp32): [xyz (N*3) | cov3d (N*9) | rgb (N*3) | opacity (N*1)] = 16N

#define C0 0.28209479177387814f
#define C1 0.4886025119029199f

__device__ __forceinline__ float sigmoidf_(float v) {
    return 1.0f / (1.0f + __expf(-v));
}

__global__ __launch_bounds__(256)
void gaussian_kernel(const float* __restrict__ view_dirs,
                     const float* __restrict__ xyz,
                     const float* __restrict__ scale_log,
                     const float* __restrict__ rot_quat,   // N x 4, float4-aligned
                     const float* __restrict__ opacity_logit,
                     const float* __restrict__ sh_coeffs,  // N x 12
                     float* __restrict__ out,
                     int n)
{
    constexpr int T = 256;
    const int tile = blockIdx.x;
    const int base = tile * T;
    int m = n - base;
    if (m > T) m = T;
    const int t = threadIdx.x;

    // Staging buffer. Input layout: xyz[0,768) vd[768,1536) sl[1536,2304) sh[2304,5376)
    // Output reuse:  cov[0,2304) rgb[2304,3072) xyzo[3072,3840)
    __shared__ float s[5376];
    float* s_xyz = s;
    float* s_vd  = s + 768;
    float* s_sl  = s + 1536;
    float* s_sh  = s + 2304;

    // ---------- staged, coalesced loads ----------
    if (m == T) {
        const float4* g4;
        float4* s4;
        g4 = reinterpret_cast<const float4*>(xyz + (size_t)base * 3);
        s4 = reinterpret_cast<float4*>(s_xyz);
        if (t < 192) s4[t] = g4[t];
        g4 = reinterpret_cast<const float4*>(view_dirs + (size_t)base * 3);
        s4 = reinterpret_cast<float4*>(s_vd);
        if (t < 192) s4[t] = g4[t];
        g4 = reinterpret_cast<const float4*>(scale_log + (size_t)base * 3);
        s4 = reinterpret_cast<float4*>(s_sl);
        if (t < 192) s4[t] = g4[t];
        g4 = reinterpret_cast<const float4*>(sh_coeffs + (size_t)base * 12);
        s4 = reinterpret_cast<float4*>(s_sh);
        s4[t]       = g4[t];
        s4[t + 256] = g4[t + 256];
        s4[t + 512] = g4[t + 512];
    } else {
        for (int k = t; k < m * 3; k += T) {
            s_xyz[k] = xyz[(size_t)base * 3 + k];
            s_vd[k]  = view_dirs[(size_t)base * 3 + k];
            s_sl[k]  = scale_log[(size_t)base * 3 + k];
        }
        for (int k = t; k < m * 12; k += T)
            s_sh[k] = sh_coeffs[(size_t)base * 12 + k];
    }
    __syncthreads();

    // ---------- per-thread compute (all inputs -> registers) ----------
    const bool active = (t < m);
    float px = 0, py = 0, pz = 0, r = 0, g = 0, b = 0, opa = 0;
    float c00 = 0, c01 = 0, c02 = 0, c11 = 0, c12 = 0, c22 = 0;

    if (active) {
        px = s_xyz[t * 3 + 0];
        py = s_xyz[t * 3 + 1];
        pz = s_xyz[t * 3 + 2];

        float dx = s_vd[t * 3 + 0];
        float dy = s_vd[t * 3 + 1];
        float dz = s_vd[t * 3 + 2];

        float s0 = __expf(s_sl[t * 3 + 0]);
        float s1 = __expf(s_sl[t * 3 + 1]);
        float s2 = __expf(s_sl[t * 3 + 2]);

        const float4* sh4 = reinterpret_cast<const float4*>(s_sh);
        float4 shr = sh4[t * 3 + 0];
        float4 shg = sh4[t * 3 + 1];
        float4 shb = sh4[t * 3 + 2];

        r = sigmoidf_(C0 * shr.x - C1 * dy * shr.y + C1 * dz * shr.z - C1 * dx * shr.w);
        g = sigmoidf_(C0 * shg.x - C1 * dy * shg.y + C1 * dz * shg.z - C1 * dx * shg.w);
        b = sigmoidf_(C0 * shb.x - C1 * dy * shb.y + C1 * dz * shb.z - C1 * dx * shb.w);

        opa = sigmoidf_(opacity_logit[base + t]);   // coalesced scalar

        float4 q = reinterpret_cast<const float4*>(rot_quat)[base + t];  // coalesced 16B
        float nrm = sqrtf(q.x * q.x + q.y * q.y + q.z * q.z + q.w * q.w);
        float inv = 1.0f / fmaxf(nrm, 1e-12f);
        float qr = q.x * inv, qx = q.y * inv, qy = q.z * inv, qz = q.w * inv;

        float R00 = 1.0f - 2.0f * (qy * qy + qz * qz);
        float R01 = 2.0f * (qx * qy - qr * qz);
        float R02 = 2.0f * (qx * qz + qr * qy);
        float R10 = 2.0f * (qx * qy + qr * qz);
        float R11 = 1.0f - 2.0f * (qx * qx + qz * qz);
        float R12 = 2.0f * (qy * qz - qr * qx);
        float R20 = 2.0f * (qx * qz - qr * qy);
        float R21 = 2.0f * (qy * qz + qr * qx);
        float R22 = 1.0f - 2.0f * (qx * qx + qy * qy);

        float M00 = R00 * s0, M01 = R01 * s1, M02 = R02 * s2;
        float M10 = R10 * s0, M11 = R11 * s1, M12 = R12 * s2;
        float M20 = R20 * s0, M21 = R21 * s1, M22 = R22 * s2;

        c00 = M00 * M00 + M01 * M01 + M02 * M02;
        c01 = M00 * M10 + M01 * M11 + M02 * M12;
        c02 = M00 * M20 + M01 * M21 + M02 * M22;
        c11 = M10 * M10 + M11 * M11 + M12 * M12;
        c12 = M10 * M20 + M11 * M21 + M12 * M22;
        c22 = M20 * M20 + M21 * M21 + M22 * M22;
    }
    __syncthreads();   // everyone done reading input staging

    // ---------- stage outputs ----------
    float* s_cov = s;          // 2304 floats
    float* s_rgb = s + 2304;   // 768
    float* s_xo  = s + 3072;   // 768
    if (active) {
        float* cv = s_cov + t * 9;
        cv[0] = c00; cv[1] = c01; cv[2] = c02;
        cv[3] = c01; cv[4] = c11; cv[5] = c12;
        cv[6] = c02; cv[7] = c12; cv[8] = c22;
        s_rgb[t * 3 + 0] = r;
        s_rgb[t * 3 + 1] = g;
        s_rgb[t * 3 + 2] = b;
        s_xo[t * 3 + 0] = px;
        s_xo[t * 3 + 1] = py;
        s_xo[t * 3 + 2] = pz;
        out[(size_t)n * 15 + base + t] = opa;   // coalesced scalar
    }
    __syncthreads();

    // ---------- coalesced float4 stores ----------
    float* out_xyz = out;
    float* out_cov = out + (size_t)n * 3;
    float* out_rgb = out + (size_t)n * 12;

    if (m == T) {
        float4* o4;
        const float4* s4;
        o4 = reinterpret_cast<float4*>(out_cov + (size_t)base * 9);
        s4 = reinterpret_cast<const float4*>(s_cov);
        o4[t]       = s4[t];
        o4[t + 256] = s4[t + 256];
        if (t < 64) o4[t + 512] = s4[t + 512];
        o4 = reinterpret_cast<float4*>(out_rgb + (size_t)base * 3);
        s4 = reinterpret_cast<const float4*>(s_rgb);
        if (t < 192) o4[t] = s4[t];
        o4 = reinterpret_cast<float4*>(out_xyz + (size_t)base * 3);
        s4 = reinterpret_cast<const float4*>(s_xo);
        if (t < 192) o4[t] = s4[t];
    } else {
        for (int k = t; k < m * 9; k += T)
            out_cov[(size_t)base * 9 + k] = s_cov[k];
        for (int k = t; k < m * 3; k += T) {
            out_rgb[(size_t)base * 3 + k] = s_rgb[k];
            out_xyz[(size_t)base * 3 + k] = s_xo[k];
        }
    }
}

extern "C" void kernel_launch(void* const* d_in, const int* in_sizes, int n_in,
                              void* d_out, int out_size) {
    const float* view_dirs     = (const float*)d_in[0];
    const float* xyz           = (const float*)d_in[1];
    const float* scale_log     = (const float*)d_in[2];
    const float* rot_quat      = (const float*)d_in[3];
    const float* opacity_logit = (const float*)d_in[4];
    const float* sh_coeffs     = (const float*)d_in[5];
    float* out = (float*)d_out;

    int n = in_sizes[1] / 3;  // xyz has N*3 elements
    int blocks = (n + 255) / 256;
    gaussian_kernel<<<blocks, 256>>>(view_dirs, xyz, scale_log, rot_quat,
                                     opacity_logit, sh_coeffs, out, n);
}

// round 3
// speedup vs baseline: 1.3764x; 1.0433x over previous
#include <cuda_runtime.h>
#include <cuda_bf16.h>

// GaussianModel preprocess, smem-staged fully-coalesced, register-lean version.
// Output layout (fp32): [xyz (N*3) | cov3d (N*9) | rgb (N*3) | opacity (N*1)] = 16N

#define C0 0.28209479177387814f
#define C1 0.4886025119029199f

__device__ __forceinline__ float sigmoidf_(float v) {
    return __fdividef(1.0f, 1.0f + __expf(-v));
}

__global__ __launch_bounds__(256, 8)
void gaussian_kernel(const float* __restrict__ view_dirs,
                     const float* __restrict__ xyz,
                     const float* __restrict__ scale_log,
                     const float* __restrict__ rot_quat,   // N x 4, float4-aligned
                     const float* __restrict__ opacity_logit,
                     const float* __restrict__ sh_coeffs,  // N x 12
                     float* __restrict__ out,
                     int n)
{
    constexpr int T = 256;
    const int base = blockIdx.x * T;
    int m = n - base;
    if (m > T) m = T;
    const int t = threadIdx.x;

    // Input staging:  vd[0,768) sl[768,1536) sh[1536,4608)
    // Output staging: cov[0,2304) rgb[2304,3072)   (reused after compute barrier)
    __shared__ float s[4608];
    float* s_vd = s;
    float* s_sl = s + 768;
    float* s_sh = s + 1536;

    float* out_xyz = out;
    float* out_cov = out + (size_t)n * 3;
    float* out_rgb = out + (size_t)n * 12;
    float* out_opa = out + (size_t)n * 15;

    // ---------- staged, coalesced loads (+ xyz direct passthrough) ----------
    if (m == T) {
        const float4* g4;
        float4* s4;
        g4 = reinterpret_cast<const float4*>(view_dirs + (size_t)base * 3);
        s4 = reinterpret_cast<float4*>(s_vd);
        if (t < 192) s4[t] = g4[t];
        g4 = reinterpret_cast<const float4*>(scale_log + (size_t)base * 3);
        s4 = reinterpret_cast<float4*>(s_sl);
        if (t < 192) s4[t] = g4[t];
        g4 = reinterpret_cast<const float4*>(sh_coeffs + (size_t)base * 12);
        s4 = reinterpret_cast<float4*>(s_sh);
        s4[t]       = g4[t];
        s4[t + 256] = g4[t + 256];
        s4[t + 512] = g4[t + 512];
        // xyz: pure passthrough, never touches smem or compute regs
        if (t < 192) {
            reinterpret_cast<float4*>(out_xyz + (size_t)base * 3)[t] =
                reinterpret_cast<const float4*>(xyz + (size_t)base * 3)[t];
        }
    } else {
        for (int k = t; k < m * 3; k += T) {
            s_vd[k] = view_dirs[(size_t)base * 3 + k];
            s_sl[k] = scale_log[(size_t)base * 3 + k];
            out_xyz[(size_t)base * 3 + k] = xyz[(size_t)base * 3 + k];
        }
        for (int k = t; k < m * 12; k += T)
            s_sh[k] = sh_coeffs[(size_t)base * 12 + k];
    }
    __syncthreads();

    // ---------- per-thread compute ----------
    const bool active = (t < m);
    float r = 0, g = 0, b = 0;
    float c00 = 0, c01 = 0, c02 = 0, c11 = 0, c12 = 0, c22 = 0;

    if (active) {
        // rgb first: release SH registers before the quat/cov block
        {
            float dx = s_vd[t * 3 + 0];
            float dy = s_vd[t * 3 + 1];
            float dz = s_vd[t * 3 + 2];
            const float4* sh4 = reinterpret_cast<const float4*>(s_sh);
            float4 shr = sh4[t * 3 + 0];
            float4 shg = sh4[t * 3 + 1];
            float4 shb = sh4[t * 3 + 2];
            r = sigmoidf_(C0 * shr.x - C1 * dy * shr.y + C1 * dz * shr.z - C1 * dx * shr.w);
            g = sigmoidf_(C0 * shg.x - C1 * dy * shg.y + C1 * dz * shg.z - C1 * dx * shg.w);
            b = sigmoidf_(C0 * shb.x - C1 * dy * shb.y + C1 * dz * shb.z - C1 * dx * shb.w);
        }

        // opacity: straight through to gmem (coalesced scalar)
        out_opa[base + t] = sigmoidf_(opacity_logit[base + t]);

        // covariance
        {
            float s0 = __expf(s_sl[t * 3 + 0]);
            float s1 = __expf(s_sl[t * 3 + 1]);
            float s2 = __expf(s_sl[t * 3 + 2]);

            float4 q = reinterpret_cast<const float4*>(rot_quat)[base + t];
            float dot = q.x * q.x + q.y * q.y + q.z * q.z + q.w * q.w;
            float inv = rsqrtf(fmaxf(dot, 1e-24f));
            float qr = q.x * inv, qx = q.y * inv, qy = q.z * inv, qz = q.w * inv;

            float M00 = (1.0f - 2.0f * (qy * qy + qz * qz)) * s0;
            float M01 = (2.0f * (qx * qy - qr * qz)) * s1;
            float M02 = (2.0f * (qx * qz + qr * qy)) * s2;
            float M10 = (2.0f * (qx * qy + qr * qz)) * s0;
            float M11 = (1.0f - 2.0f * (qx * qx + qz * qz)) * s1;
            float M12 = (2.0f * (qy * qz - qr * qx)) * s2;
            float M20 = (2.0f * (qx * qz - qr * qy)) * s0;
            float M21 = (2.0f * (qy * qz + qr * qx)) * s1;
            float M22 = (1.0f - 2.0f * (qx * qx + qy * qy)) * s2;

            c00 = M00 * M00 + M01 * M01 + M02 * M02;
            c01 = M00 * M10 + M01 * M11 + M02 * M12;
            c02 = M00 * M20 + M01 * M21 + M02 * M22;
            c11 = M10 * M10 + M11 * M11 + M12 * M12;
            c12 = M10 * M20 + M11 * M21 + M12 * M22;
            c22 = M20 * M20 + M21 * M21 + M22 * M22;
        }
    }
    __syncthreads();   // all input staging consumed

    // ---------- stage outputs (reuse smem) ----------
    float* s_cov = s;          // 2304 floats
    float* s_rgb = s + 2304;   // 768 floats
    if (active) {
        float* cv = s_cov + t * 9;
        cv[0] = c00; cv[1] = c01; cv[2] = c02;
        cv[3] = c01; cv[4] = c11; cv[5] = c12;
        cv[6] = c02; cv[7] = c12; cv[8] = c22;
        s_rgb[t * 3 + 0] = r;
        s_rgb[t * 3 + 1] = g;
        s_rgb[t * 3 + 2] = b;
    }
    __syncthreads();

    // ---------- coalesced float4 stores ----------
    if (m == T) {
        float4* o4;
        const float4* s4;
        o4 = reinterpret_cast<float4*>(out_cov + (size_t)base * 9);
        s4 = reinterpret_cast<const float4*>(s_cov);
        o4[t]       = s4[t];
        o4[t + 256] = s4[t + 256];
        if (t < 64) o4[t + 512] = s4[t + 512];
        o4 = reinterpret_cast<float4*>(out_rgb + (size_t)base * 3);
        s4 = reinterpret_cast<const float4*>(s_rgb);
        if (t < 192) o4[t] = s4[t];
    } else {
        for (int k = t; k < m * 9; k += T)
            out_cov[(size_t)base * 9 + k] = s_cov[k];
        for (int k = t; k < m * 3; k += T)
            out_rgb[(size_t)base * 3 + k] = s_rgb[k];
    }
}

extern "C" void kernel_launch(void* const* d_in, const int* in_sizes, int n_in,
                              void* d_out, int out_size) {
    const float* view_dirs     = (const float*)d_in[0];
    const float* xyz           = (const float*)d_in[1];
    const float* scale_log     = (const float*)d_in[2];
    const float* rot_quat      = (const float*)d_in[3];
    const float* opacity_logit = (const float*)d_in[4];
    const float* sh_coeffs     = (const float*)d_in[5];
    float* out = (float*)d_out;

    int n = in_sizes[1] / 3;  // xyz has N*3 elements
    int blocks = (n + 255) / 256;
    gaussian_kernel<<<blocks, 256>>>(view_dirs, xyz, scale_log, rot_quat,
                                     opacity_logit, sh_coeffs, out, n);
}

// round 4
// speedup vs baseline: 1.4132x; 1.0267x over previous
#include <cuda_runtime.h>
#include <cuda_bf16.h>
#include <cstdint>

// GaussianModel preprocess — TMA-staged version.
// Output layout (fp32): [xyz (N*3) | cov3d (N*9) | rgb (N*3) | opacity (N*1)] = 16N

#define C0 0.28209479177387814f
#define C1 0.4886025119029199f

__device__ __forceinline__ float sigmoidf_(float v) {
    return __fdividef(1.0f, 1.0f + __expf(-v));
}

__device__ __forceinline__ uint32_t smem_u32(const void* p) {
    uint32_t a;
    asm("{ .reg .u64 t; cvta.to.shared.u64 t, %1; cvt.u32.u64 %0, t; }"
        : "=r"(a) : "l"(p));
    return a;
}

__device__ __forceinline__ void bulk_g2s(uint32_t smem_addr, const void* gmem,
                                         uint32_t bytes, uint32_t mbar) {
    asm volatile(
        "cp.async.bulk.shared::cta.global.mbarrier::complete_tx::bytes [%0], [%1], %2, [%3];"
        :: "r"(smem_addr), "l"(gmem), "r"(bytes), "r"(mbar) : "memory");
}

__device__ __forceinline__ void bulk_s2g(void* gmem, uint32_t smem_addr, uint32_t bytes) {
    asm volatile(
        "cp.async.bulk.global.shared::cta.bulk_group [%0], [%1], %2;"
        :: "l"(gmem), "r"(smem_addr), "r"(bytes) : "memory");
}

__device__ __forceinline__ void mbar_init(uint32_t mbar, uint32_t count) {
    asm volatile("mbarrier.init.shared.b64 [%0], %1;" :: "r"(mbar), "r"(count) : "memory");
}

__device__ __forceinline__ void mbar_expect_tx(uint32_t mbar, uint32_t bytes) {
    asm volatile("mbarrier.arrive.expect_tx.shared.b64 _, [%0], %1;"
                 :: "r"(mbar), "r"(bytes) : "memory");
}

__device__ __forceinline__ void mbar_wait(uint32_t mbar, uint32_t parity) {
    asm volatile(
        "{\n\t"
        ".reg .pred P1;\n\t"
        "WAIT_LOOP_%=:\n\t"
        "mbarrier.try_wait.parity.acquire.cta.shared::cta.b64 P1, [%0], %1, 0x989680;\n\t"
        "@P1 bra.uni WAIT_DONE_%=;\n\t"
        "bra.uni WAIT_LOOP_%=;\n\t"
        "WAIT_DONE_%=:\n\t"
        "}"
        :: "r"(mbar), "r"(parity) : "memory");
}

__global__ __launch_bounds__(256, 8)
void gaussian_kernel(const float* __restrict__ view_dirs,
                     const float* __restrict__ xyz,
                     const float* __restrict__ scale_log,
                     const float* __restrict__ rot_quat,
                     const float* __restrict__ opacity_logit,
                     const float* __restrict__ sh_coeffs,
                     float* __restrict__ out,
                     int n, int aligned)
{
    constexpr int T = 256;
    const int base = blockIdx.x * T;
    int m = n - base;
    if (m > T) m = T;
    const int t = threadIdx.x;

    float* out_xyz = out;
    float* out_cov = out + (size_t)n * 3;
    float* out_rgb = out + (size_t)n * 12;
    float* out_opa = out + (size_t)n * 15;

    // ---------------- fallback (tail tile or misaligned buffers) ----------------
    if (m != T || !aligned) {
        if (t < m) {
            int i = base + t;
            out_xyz[(size_t)i * 3 + 0] = xyz[(size_t)i * 3 + 0];
            out_xyz[(size_t)i * 3 + 1] = xyz[(size_t)i * 3 + 1];
            out_xyz[(size_t)i * 3 + 2] = xyz[(size_t)i * 3 + 2];

            float dx = view_dirs[(size_t)i * 3 + 0];
            float dy = view_dirs[(size_t)i * 3 + 1];
            float dz = view_dirs[(size_t)i * 3 + 2];
            const float* sh = sh_coeffs + (size_t)i * 12;
            for (int c = 0; c < 3; c++) {
                out_rgb[(size_t)i * 3 + c] =
                    sigmoidf_(C0 * sh[c * 4 + 0] - C1 * dy * sh[c * 4 + 1]
                              + C1 * dz * sh[c * 4 + 2] - C1 * dx * sh[c * 4 + 3]);
            }
            out_opa[i] = sigmoidf_(opacity_logit[i]);

            float s0 = __expf(scale_log[(size_t)i * 3 + 0]);
            float s1 = __expf(scale_log[(size_t)i * 3 + 1]);
            float s2 = __expf(scale_log[(size_t)i * 3 + 2]);
            float qw = rot_quat[(size_t)i * 4 + 0], qa = rot_quat[(size_t)i * 4 + 1];
            float qb = rot_quat[(size_t)i * 4 + 2], qc = rot_quat[(size_t)i * 4 + 3];
            float inv = rsqrtf(fmaxf(qw * qw + qa * qa + qb * qb + qc * qc, 1e-24f));
            float qr = qw * inv, qx = qa * inv, qy = qb * inv, qz = qc * inv;
            float M00 = (1.0f - 2.0f * (qy * qy + qz * qz)) * s0;
            float M01 = (2.0f * (qx * qy - qr * qz)) * s1;
            float M02 = (2.0f * (qx * qz + qr * qy)) * s2;
            float M10 = (2.0f * (qx * qy + qr * qz)) * s0;
            float M11 = (1.0f - 2.0f * (qx * qx + qz * qz)) * s1;
            float M12 = (2.0f * (qy * qz - qr * qx)) * s2;
            float M20 = (2.0f * (qx * qz - qr * qy)) * s0;
            float M21 = (2.0f * (qy * qz + qr * qx)) * s1;
            float M22 = (1.0f - 2.0f * (qx * qx + qy * qy)) * s2;
            float* cv = out_cov + (size_t)i * 9;
            cv[0] = M00 * M00 + M01 * M01 + M02 * M02;
            cv[1] = M00 * M10 + M01 * M11 + M02 * M12;
            cv[2] = M00 * M20 + M01 * M21 + M02 * M22;
            cv[3] = cv[1];
            cv[4] = M10 * M10 + M11 * M11 + M12 * M12;
            cv[5] = M10 * M20 + M11 * M21 + M12 * M22;
            cv[6] = cv[2];
            cv[7] = cv[5];
            cv[8] = M20 * M20 + M21 * M21 + M22 * M22;
        }
        return;
    }

    // ---------------- TMA path (full tile) ----------------
    // smem floats: xyz[0,768) vd[768,1536) sl[1536,2304) sh[2304,5376)
    // output staging reuses vd/sl/sh region: cov[768,3072) rgb[3072,3840)
    __shared__ __align__(128) float s[5376];
    __shared__ __align__(8) uint64_t mbar_storage;

    float* s_xyz = s;
    float* s_vd  = s + 768;
    float* s_sl  = s + 1536;
    float* s_sh  = s + 2304;
    const uint32_t mbar = smem_u32(&mbar_storage);

    if (t == 0) mbar_init(mbar, 1);
    __syncthreads();

    if (t == 0) {
        constexpr uint32_t BYTES = (768 + 768 + 768 + 3072) * 4;  // 21504
        mbar_expect_tx(mbar, BYTES);
        bulk_g2s(smem_u32(s_xyz), xyz + (size_t)base * 3, 768 * 4, mbar);
        bulk_g2s(smem_u32(s_vd),  view_dirs + (size_t)base * 3, 768 * 4, mbar);
        bulk_g2s(smem_u32(s_sl),  scale_log + (size_t)base * 3, 768 * 4, mbar);
        bulk_g2s(smem_u32(s_sh),  sh_coeffs + (size_t)base * 12, 3072 * 4, mbar);
    }

    // overlap with TMA: quat + opacity via regular coalesced loads
    float4 q = reinterpret_cast<const float4*>(rot_quat)[base + t];
    float opa = sigmoidf_(opacity_logit[base + t]);
    out_opa[base + t] = opa;

    mbar_wait(mbar, 0);

    // xyz passthrough: bounce straight back out via TMA (region not reused below)
    if (t == 0) {
        bulk_s2g(out_xyz + (size_t)base * 3, smem_u32(s_xyz), 768 * 4);
    }

    // ---------------- compute ----------------
    float r, g, b, c00, c01, c02, c11, c12, c22;
    {
        float dx = s_vd[t * 3 + 0];
        float dy = s_vd[t * 3 + 1];
        float dz = s_vd[t * 3 + 2];
        const float4* sh4 = reinterpret_cast<const float4*>(s_sh);
        float4 shr = sh4[t * 3 + 0];
        float4 shg = sh4[t * 3 + 1];
        float4 shb = sh4[t * 3 + 2];
        r = sigmoidf_(C0 * shr.x - C1 * dy * shr.y + C1 * dz * shr.z - C1 * dx * shr.w);
        g = sigmoidf_(C0 * shg.x - C1 * dy * shg.y + C1 * dz * shg.z - C1 * dx * shg.w);
        b = sigmoidf_(C0 * shb.x - C1 * dy * shb.y + C1 * dz * shb.z - C1 * dx * shb.w);
    }
    {
        float s0 = __expf(s_sl[t * 3 + 0]);
        float s1 = __expf(s_sl[t * 3 + 1]);
        float s2 = __expf(s_sl[t * 3 + 2]);
        float inv = rsqrtf(fmaxf(q.x * q.x + q.y * q.y + q.z * q.z + q.w * q.w, 1e-24f));
        float qr = q.x * inv, qx = q.y * inv, qy = q.z * inv, qz = q.w * inv;

        float M00 = (1.0f - 2.0f * (qy * qy + qz * qz)) * s0;
        float M01 = (2.0f * (qx * qy - qr * qz)) * s1;
        float M02 = (2.0f * (qx * qz + qr * qy)) * s2;
        float M10 = (2.0f * (qx * qy + qr * qz)) * s0;
        float M11 = (1.0f - 2.0f * (qx * qx + qz * qz)) * s1;
        float M12 = (2.0f * (qy * qz - qr * qx)) * s2;
        float M20 = (2.0f * (qx * qz - qr * qy)) * s0;
        float M21 = (2.0f * (qy * qz + qr * qx)) * s1;
        float M22 = (1.0f - 2.0f * (qx * qx + qy * qy)) * s2;

        c00 = M00 * M00 + M01 * M01 + M02 * M02;
        c01 = M00 * M10 + M01 * M11 + M02 * M12;
        c02 = M00 * M20 + M01 * M21 + M02 * M22;
        c11 = M10 * M10 + M11 * M11 + M12 * M12;
        c12 = M10 * M20 + M11 * M21 + M12 * M22;
        c22 = M20 * M20 + M21 * M21 + M22 * M22;
    }
    __syncthreads();   // everyone done reading vd/sl/sh staging

    // ---------------- stage outputs, TMA store ----------------
    float* s_cov = s + 768;    // 2304 floats
    float* s_rgb = s + 3072;   // 768 floats
    {
        float* cv = s_cov + t * 9;
        cv[0] = c00; cv[1] = c01; cv[2] = c02;
        cv[3] = c01; cv[4] = c11; cv[5] = c12;
        cv[6] = c02; cv[7] = c12; cv[8] = c22;
        s_rgb[t * 3 + 0] = r;
        s_rgb[t * 3 + 1] = g;
        s_rgb[t * 3 + 2] = b;
    }
    __syncthreads();

    if (t == 0) {
        asm volatile("fence.proxy.async.shared::cta;" ::: "memory");
        bulk_s2g(out_cov + (size_t)base * 9, smem_u32(s_cov), 2304 * 4);
        bulk_s2g(out_rgb + (size_t)base * 3, smem_u32(s_rgb), 768 * 4);
        asm volatile("cp.async.bulk.commit_group;" ::: "memory");
        asm volatile("cp.async.bulk.wait_group.read 0;" ::: "memory");
    }
}

extern "C" void kernel_launch(void* const* d_in, const int* in_sizes, int n_in,
                              void* d_out, int out_size) {
    const float* view_dirs     = (const float*)d_in[0];
    const float* xyz           = (const float*)d_in[1];
    const float* scale_log     = (const float*)d_in[2];
    const float* rot_quat      = (const float*)d_in[3];
    const float* opacity_logit = (const float*)d_in[4];
    const float* sh_coeffs     = (const float*)d_in[5];
    float* out = (float*)d_out;

    int n = in_sizes[1] / 3;
    // TMA path requires 16B alignment of all bulk segment bases: n % 4 == 0
    // plus 16B-aligned input pointers (cudaMalloc guarantees 256B).
    int aligned = ((n & 3) == 0);

    int blocks = (n + 255) / 256;
    gaussian_kernel<<<blocks, 256>>>(view_dirs, xyz, scale_log, rot_quat,
                                     opacity_logit, sh_coeffs, out, n, aligned);
}

// round 5
// speedup vs baseline: 1.4190x; 1.0042x over previous
#include <cuda_runtime.h>
#include <cuda_bf16.h>
#include <cstdint>

// GaussianModel preprocess — TMA double-buffered, 2 tiles per CTA.
// Output layout (fp32): [xyz (N*3) | cov3d (N*9) | rgb (N*3) | opacity (N*1)] = 16N

#define C0 0.28209479177387814f
#define C1 0.4886025119029199f

__device__ __forceinline__ float sigmoidf_(float v) {
    return __fdividef(1.0f, 1.0f + __expf(-v));
}

__device__ __forceinline__ uint32_t smem_u32(const void* p) {
    uint32_t a;
    asm("{ .reg .u64 t; cvta.to.shared.u64 t, %1; cvt.u32.u64 %0, t; }"
        : "=r"(a) : "l"(p));
    return a;
}

__device__ __forceinline__ void bulk_g2s(uint32_t smem_addr, const void* gmem,
                                         uint32_t bytes, uint32_t mbar) {
    asm volatile(
        "cp.async.bulk.shared::cta.global.mbarrier::complete_tx::bytes [%0], [%1], %2, [%3];"
        :: "r"(smem_addr), "l"(gmem), "r"(bytes), "r"(mbar) : "memory");
}

__device__ __forceinline__ void bulk_s2g(void* gmem, uint32_t smem_addr, uint32_t bytes) {
    asm volatile(
        "cp.async.bulk.global.shared::cta.bulk_group [%0], [%1], %2;"
        :: "l"(gmem), "r"(smem_addr), "r"(bytes) : "memory");
}

__device__ __forceinline__ void mbar_init(uint32_t mbar, uint32_t count) {
    asm volatile("mbarrier.init.shared.b64 [%0], %1;" :: "r"(mbar), "r"(count) : "memory");
}

__device__ __forceinline__ void mbar_expect_tx(uint32_t mbar, uint32_t bytes) {
    asm volatile("mbarrier.arrive.expect_tx.shared.b64 _, [%0], %1;"
                 :: "r"(mbar), "r"(bytes) : "memory");
}

__device__ __forceinline__ void mbar_wait(uint32_t mbar, uint32_t parity) {
    asm volatile(
        "{\n\t"
        ".reg .pred P1;\n\t"
        "WAIT_LOOP_%=:\n\t"
        "mbarrier.try_wait.parity.acquire.cta.shared::cta.b64 P1, [%0], %1, 0x989680;\n\t"
        "@P1 bra.uni WAIT_DONE_%=;\n\t"
        "bra.uni WAIT_LOOP_%=;\n\t"
        "WAIT_DONE_%=:\n\t"
        "}"
        :: "r"(mbar), "r"(parity) : "memory");
}

__global__ __launch_bounds__(256, 5)
void gaussian_kernel(const float* __restrict__ view_dirs,
                     const float* __restrict__ xyz,
                     const float* __restrict__ scale_log,
                     const float* __restrict__ rot_quat,
                     const float* __restrict__ opacity_logit,
                     const float* __restrict__ sh_coeffs,
                     float* __restrict__ out,
                     int n, int ntiles, int aligned)
{
    constexpr int T = 256;
    const int t = threadIdx.x;
    const int tile0 = blockIdx.x * 2;

    float* out_xyz = out;
    float* out_cov = out + (size_t)n * 3;
    float* out_rgb = out + (size_t)n * 12;
    float* out_opa = out + (size_t)n * 15;

    // Two full staging buffers. Per buffer (floats):
    //   in:  xyz[0,768) vd[768,1536) sl[1536,2304) sh[2304,5376)
    //   out: cov reuses [768,3072), rgb reuses [3072,3840); xyz region untouched.
    __shared__ __align__(128) float sbuf[2][5376];
    __shared__ __align__(8) uint64_t mbar_storage[2];

    const uint32_t mb0 = smem_u32(&mbar_storage[0]);
    const uint32_t mb1 = smem_u32(&mbar_storage[1]);

    if (t == 0) { mbar_init(mb0, 1); mbar_init(mb1, 1); }
    __syncthreads();

    // ---- issue both tiles' loads up-front ----
    if (t == 0) {
        #pragma unroll
        for (int w = 0; w < 2; w++) {
            int tile = tile0 + w;
            if (tile >= ntiles) break;
            int base = tile * T;
            bool full = (base + T <= n) && aligned;
            if (!full) break;
            uint32_t mb = w ? mb1 : mb0;
            float* b = sbuf[w];
            mbar_expect_tx(mb, (768 + 768 + 768 + 3072) * 4);
            bulk_g2s(smem_u32(b),        xyz       + (size_t)base * 3,  768 * 4, mb);
            bulk_g2s(smem_u32(b + 768),  view_dirs + (size_t)base * 3,  768 * 4, mb);
            bulk_g2s(smem_u32(b + 1536), scale_log + (size_t)base * 3,  768 * 4, mb);
            bulk_g2s(smem_u32(b + 2304), sh_coeffs + (size_t)base * 12, 3072 * 4, mb);
        }
    }

    #pragma unroll
    for (int w = 0; w < 2; w++) {
        int tile = tile0 + w;
        if (tile >= ntiles) break;
        const int base = tile * T;
        int m = n - base;
        if (m > T) m = T;

        if (m == T && aligned) {
            // ---------------- TMA path ----------------
            float* s   = sbuf[w];
            float* s_vd = s + 768;
            float* s_sl = s + 1536;
            float* s_sh = s + 2304;
            const uint32_t mb = w ? mb1 : mb0;

            // overlap with in-flight TMA: quat + opacity via LDG
            float4 q = reinterpret_cast<const float4*>(rot_quat)[base + t];
            out_opa[base + t] = sigmoidf_(opacity_logit[base + t]);

            mbar_wait(mb, 0);

            // xyz passthrough bounce (region [0,768) never overwritten)
            if (t == 0) bulk_s2g(out_xyz + (size_t)base * 3, smem_u32(s), 768 * 4);

            float r, g, b2, c00, c01, c02, c11, c12, c22;
            {
                float dx = s_vd[t * 3 + 0];
                float dy = s_vd[t * 3 + 1];
                float dz = s_vd[t * 3 + 2];
                const float4* sh4 = reinterpret_cast<const float4*>(s_sh);
                float4 shr = sh4[t * 3 + 0];
                float4 shg = sh4[t * 3 + 1];
                float4 shb = sh4[t * 3 + 2];
                r  = sigmoidf_(C0 * shr.x - C1 * dy * shr.y + C1 * dz * shr.z - C1 * dx * shr.w);
                g  = sigmoidf_(C0 * shg.x - C1 * dy * shg.y + C1 * dz * shg.z - C1 * dx * shg.w);
                b2 = sigmoidf_(C0 * shb.x - C1 * dy * shb.y + C1 * dz * shb.z - C1 * dx * shb.w);
            }
            {
                float s0 = __expf(s_sl[t * 3 + 0]);
                float s1 = __expf(s_sl[t * 3 + 1]);
                float s2 = __expf(s_sl[t * 3 + 2]);
                float inv = rsqrtf(fmaxf(q.x * q.x + q.y * q.y + q.z * q.z + q.w * q.w, 1e-24f));
                float qr = q.x * inv, qx = q.y * inv, qy = q.z * inv, qz = q.w * inv;

                float M00 = (1.0f - 2.0f * (qy * qy + qz * qz)) * s0;
                float M01 = (2.0f * (qx * qy - qr * qz)) * s1;
                float M02 = (2.0f * (qx * qz + qr * qy)) * s2;
                float M10 = (2.0f * (qx * qy + qr * qz)) * s0;
                float M11 = (1.0f - 2.0f * (qx * qx + qz * qz)) * s1;
                float M12 = (2.0f * (qy * qz - qr * qx)) * s2;
                float M20 = (2.0f * (qx * qz - qr * qy)) * s0;
                float M21 = (2.0f * (qy * qz + qr * qx)) * s1;
                float M22 = (1.0f - 2.0f * (qx * qx + qy * qy)) * s2;

                c00 = M00 * M00 + M01 * M01 + M02 * M02;
                c01 = M00 * M10 + M01 * M11 + M02 * M12;
                c02 = M00 * M20 + M01 * M21 + M02 * M22;
                c11 = M10 * M10 + M11 * M11 + M12 * M12;
                c12 = M10 * M20 + M11 * M21 + M12 * M22;
                c22 = M20 * M20 + M21 * M21 + M22 * M22;
            }
            __syncthreads();   // staging consumed

            float* s_cov = s + 768;    // 2304 floats
            float* s_rgb = s + 3072;   // 768 floats
            {
                float* cv = s_cov + t * 9;
                cv[0] = c00; cv[1] = c01; cv[2] = c02;
                cv[3] = c01; cv[4] = c11; cv[5] = c12;
                cv[6] = c02; cv[7] = c12; cv[8] = c22;
                s_rgb[t * 3 + 0] = r;
                s_rgb[t * 3 + 1] = g;
                s_rgb[t * 3 + 2] = b2;
            }
            __syncthreads();

            if (t == 0) {
                asm volatile("fence.proxy.async.shared::cta;" ::: "memory");
                bulk_s2g(out_cov + (size_t)base * 9, smem_u32(s_cov), 2304 * 4);
                bulk_s2g(out_rgb + (size_t)base * 3, smem_u32(s_rgb), 768 * 4);
                asm volatile("cp.async.bulk.commit_group;" ::: "memory");
                // no wait here — overlaps the next tile's compute
            }
        } else {
            // ---------------- fallback (tail tile or misaligned) ----------------
            if (t < m) {
                int i = base + t;
                out_xyz[(size_t)i * 3 + 0] = xyz[(size_t)i * 3 + 0];
                out_xyz[(size_t)i * 3 + 1] = xyz[(size_t)i * 3 + 1];
                out_xyz[(size_t)i * 3 + 2] = xyz[(size_t)i * 3 + 2];

                float dx = view_dirs[(size_t)i * 3 + 0];
                float dy = view_dirs[(size_t)i * 3 + 1];
                float dz = view_dirs[(size_t)i * 3 + 2];
                const float* sh = sh_coeffs + (size_t)i * 12;
                for (int c = 0; c < 3; c++) {
                    out_rgb[(size_t)i * 3 + c] =
                        sigmoidf_(C0 * sh[c * 4 + 0] - C1 * dy * sh[c * 4 + 1]
                                  + C1 * dz * sh[c * 4 + 2] - C1 * dx * sh[c * 4 + 3]);
                }
                out_opa[i] = sigmoidf_(opacity_logit[i]);

                float s0 = __expf(scale_log[(size_t)i * 3 + 0]);
                float s1 = __expf(scale_log[(size_t)i * 3 + 1]);
                float s2 = __expf(scale_log[(size_t)i * 3 + 2]);
                float qw = rot_quat[(size_t)i * 4 + 0], qa = rot_quat[(size_t)i * 4 + 1];
                float qb = rot_quat[(size_t)i * 4 + 2], qc = rot_quat[(size_t)i * 4 + 3];
                float inv = rsqrtf(fmaxf(qw * qw + qa * qa + qb * qb + qc * qc, 1e-24f));
                float qr = qw * inv, qx = qa * inv, qy = qb * inv, qz = qc * inv;
                float M00 = (1.0f - 2.0f * (qy * qy + qz * qz)) * s0;
                float M01 = (2.0f * (qx * qy - qr * qz)) * s1;
                float M02 = (2.0f * (qx * qz + qr * qy)) * s2;
                float M10 = (2.0f * (qx * qy + qr * qz)) * s0;
                float M11 = (1.0f - 2.0f * (qx * qx + qz * qz)) * s1;
                float M12 = (2.0f * (qy * qz - qr * qx)) * s2;
                float M20 = (2.0f * (qx * qz - qr * qy)) * s0;
                float M21 = (2.0f * (qy * qz + qr * qx)) * s1;
                float M22 = (1.0f - 2.0f * (qx * qx + qy * qy)) * s2;
                float* cv = out_cov + (size_t)i * 9;
                cv[0] = M00 * M00 + M01 * M01 + M02 * M02;
                cv[1] = M00 * M10 + M01 * M11 + M02 * M12;
                cv[2] = M00 * M20 + M01 * M21 + M02 * M22;
                cv[3] = cv[1];
                cv[4] = M10 * M10 + M11 * M11 + M12 * M12;
                cv[5] = M10 * M20 + M11 * M21 + M12 * M22;
                cv[6] = cv[2];
                cv[7] = cv[5];
                cv[8] = M20 * M20 + M21 * M21 + M22 * M22;
            }
        }
    }

    // drain all pending bulk stores before smem is released
    if (t == 0) {
        asm volatile("cp.async.bulk.wait_group.read 0;" ::: "memory");
    }
}

extern "C" void kernel_launch(void* const* d_in, const int* in_sizes, int n_in,
                              void* d_out, int out_size) {
    const float* view_dirs     = (const float*)d_in[0];
    const float* xyz           = (const float*)d_in[1];
    const float* scale_log     = (const float*)d_in[2];
    const float* rot_quat      = (const float*)d_in[3];
    const float* opacity_logit = (const float*)d_in[4];
    const float* sh_coeffs     = (const float*)d_in[5];
    float* out = (float*)d_out;

    int n = in_sizes[1] / 3;
    int ntiles = (n + 255) / 256;
    int aligned = ((n & 3) == 0);   // output segment bases 16B-aligned

    int blocks = (ntiles + 1) / 2;  // 2 tiles per CTA
    gaussian_kernel<<<blocks, 256>>>(view_dirs, xyz, scale_log, rot_quat,
                                     opacity_logit, sh_coeffs, out, n, ntiles, aligned);
}

// round 6
// speedup vs baseline: 1.4207x; 1.0012x over previous
#include <cuda_runtime.h>
#include <cuda_bf16.h>
#include <cstdint>

// GaussianModel preprocess — TMA-staged + L2 evict_first streaming hints.
// Output layout (fp32): [xyz (N*3) | cov3d (N*9) | rgb (N*3) | opacity (N*1)] = 16N

#define C0 0.28209479177387814f
#define C1 0.4886025119029199f

__device__ __forceinline__ float sigmoidf_(float v) {
    return __fdividef(1.0f, 1.0f + __expf(-v));
}

__device__ __forceinline__ uint32_t smem_u32(const void* p) {
    uint32_t a;
    asm("{ .reg .u64 t; cvta.to.shared.u64 t, %1; cvt.u32.u64 %0, t; }"
        : "=r"(a) : "l"(p));
    return a;
}

__device__ __forceinline__ uint64_t evict_first_policy() {
    uint64_t pol;
    asm("createpolicy.fractional.L2::evict_first.b64 %0, 1.0;" : "=l"(pol));
    return pol;
}

__device__ __forceinline__ void bulk_g2s(uint32_t smem_addr, const void* gmem,
                                         uint32_t bytes, uint32_t mbar, uint64_t pol) {
    asm volatile(
        "cp.async.bulk.shared::cta.global.mbarrier::complete_tx::bytes.L2::cache_hint"
        " [%0], [%1], %2, [%3], %4;"
        :: "r"(smem_addr), "l"(gmem), "r"(bytes), "r"(mbar), "l"(pol) : "memory");
}

__device__ __forceinline__ void bulk_s2g(void* gmem, uint32_t smem_addr,
                                         uint32_t bytes, uint64_t pol) {
    asm volatile(
        "cp.async.bulk.global.shared::cta.bulk_group.L2::cache_hint [%0], [%1], %2, %3;"
        :: "l"(gmem), "r"(smem_addr), "r"(bytes), "l"(pol) : "memory");
}

__device__ __forceinline__ void mbar_init(uint32_t mbar, uint32_t count) {
    asm volatile("mbarrier.init.shared.b64 [%0], %1;" :: "r"(mbar), "r"(count) : "memory");
}

__device__ __forceinline__ void mbar_expect_tx(uint32_t mbar, uint32_t bytes) {
    asm volatile("mbarrier.arrive.expect_tx.shared.b64 _, [%0], %1;"
                 :: "r"(mbar), "r"(bytes) : "memory");
}

__device__ __forceinline__ void mbar_wait(uint32_t mbar, uint32_t parity) {
    asm volatile(
        "{\n\t"
        ".reg .pred P1;\n\t"
        "WAIT_LOOP_%=:\n\t"
        "mbarrier.try_wait.parity.acquire.cta.shared::cta.b64 P1, [%0], %1, 0x989680;\n\t"
        "@P1 bra.uni WAIT_DONE_%=;\n\t"
        "bra.uni WAIT_LOOP_%=;\n\t"
        "WAIT_DONE_%=:\n\t"
        "}"
        :: "r"(mbar), "r"(parity) : "memory");
}

__global__ __launch_bounds__(256, 8)
void gaussian_kernel(const float* __restrict__ view_dirs,
                     const float* __restrict__ xyz,
                     const float* __restrict__ scale_log,
                     const float* __restrict__ rot_quat,
                     const float* __restrict__ opacity_logit,
                     const float* __restrict__ sh_coeffs,
                     float* __restrict__ out,
                     int n, int aligned)
{
    constexpr int T = 256;
    const int base = blockIdx.x * T;
    int m = n - base;
    if (m > T) m = T;
    const int t = threadIdx.x;

    float* out_xyz = out;
    float* out_cov = out + (size_t)n * 3;
    float* out_rgb = out + (size_t)n * 12;
    float* out_opa = out + (size_t)n * 15;

    // ---------------- fallback (tail tile or misaligned buffers) ----------------
    if (m != T || !aligned) {
        if (t < m) {
            int i = base + t;
            out_xyz[(size_t)i * 3 + 0] = xyz[(size_t)i * 3 + 0];
            out_xyz[(size_t)i * 3 + 1] = xyz[(size_t)i * 3 + 1];
            out_xyz[(size_t)i * 3 + 2] = xyz[(size_t)i * 3 + 2];

            float dx = view_dirs[(size_t)i * 3 + 0];
            float dy = view_dirs[(size_t)i * 3 + 1];
            float dz = view_dirs[(size_t)i * 3 + 2];
            const float* sh = sh_coeffs + (size_t)i * 12;
            for (int c = 0; c < 3; c++) {
                out_rgb[(size_t)i * 3 + c] =
                    sigmoidf_(C0 * sh[c * 4 + 0] - C1 * dy * sh[c * 4 + 1]
                              + C1 * dz * sh[c * 4 + 2] - C1 * dx * sh[c * 4 + 3]);
            }
            out_opa[i] = sigmoidf_(opacity_logit[i]);

            float s0 = __expf(scale_log[(size_t)i * 3 + 0]);
            float s1 = __expf(scale_log[(size_t)i * 3 + 1]);
            float s2 = __expf(scale_log[(size_t)i * 3 + 2]);
            float qw = rot_quat[(size_t)i * 4 + 0], qa = rot_quat[(size_t)i * 4 + 1];
            float qb = rot_quat[(size_t)i * 4 + 2], qc = rot_quat[(size_t)i * 4 + 3];
            float inv = rsqrtf(fmaxf(qw * qw + qa * qa + qb * qb + qc * qc, 1e-24f));
            float qr = qw * inv, qx = qa * inv, qy = qb * inv, qz = qc * inv;
            float M00 = (1.0f - 2.0f * (qy * qy + qz * qz)) * s0;
            float M01 = (2.0f * (qx * qy - qr * qz)) * s1;
            float M02 = (2.0f * (qx * qz + qr * qy)) * s2;
            float M10 = (2.0f * (qx * qy + qr * qz)) * s0;
            float M11 = (1.0f - 2.0f * (qx * qx + qz * qz)) * s1;
            float M12 = (2.0f * (qy * qz - qr * qx)) * s2;
            float M20 = (2.0f * (qx * qz - qr * qy)) * s0;
            float M21 = (2.0f * (qy * qz + qr * qx)) * s1;
            float M22 = (1.0f - 2.0f * (qx * qx + qy * qy)) * s2;
            float* cv = out_cov + (size_t)i * 9;
            cv[0] = M00 * M00 + M01 * M01 + M02 * M02;
            cv[1] = M00 * M10 + M01 * M11 + M02 * M12;
            cv[2] = M00 * M20 + M01 * M21 + M02 * M22;
            cv[3] = cv[1];
            cv[4] = M10 * M10 + M11 * M11 + M12 * M12;
            cv[5] = M10 * M20 + M11 * M21 + M12 * M22;
            cv[6] = cv[2];
            cv[7] = cv[5];
            cv[8] = M20 * M20 + M21 * M21 + M22 * M22;
        }
        return;
    }

    // ---------------- TMA path (full tile) ----------------
    // smem floats: xyz[0,768) vd[768,1536) sl[1536,2304) sh[2304,5376)
    // output staging reuses: cov[768,3072) rgb[3072,3840); xyz region untouched.
    __shared__ __align__(128) float s[5376];
    __shared__ __align__(8) uint64_t mbar_storage;

    float* s_xyz = s;
    float* s_vd  = s + 768;
    float* s_sl  = s + 1536;
    float* s_sh  = s + 2304;
    const uint32_t mbar = smem_u32(&mbar_storage);
    const uint64_t pol = evict_first_policy();

    if (t == 0) mbar_init(mbar, 1);
    __syncthreads();

    if (t == 0) {
        constexpr uint32_t BYTES = (768 + 768 + 768 + 3072) * 4;  // 21504
        mbar_expect_tx(mbar, BYTES);
        bulk_g2s(smem_u32(s_xyz), xyz + (size_t)base * 3,       768 * 4,  mbar, pol);
        bulk_g2s(smem_u32(s_vd),  view_dirs + (size_t)base * 3,  768 * 4,  mbar, pol);
        bulk_g2s(smem_u32(s_sl),  scale_log + (size_t)base * 3,  768 * 4,  mbar, pol);
        bulk_g2s(smem_u32(s_sh),  sh_coeffs + (size_t)base * 12, 3072 * 4, mbar, pol);
    }

    // overlap with TMA: quat + opacity via streaming LDG/STG
    float4 q = __ldcs(reinterpret_cast<const float4*>(rot_quat) + base + t);
    __stcs(out_opa + base + t, sigmoidf_(__ldcs(opacity_logit + base + t)));

    mbar_wait(mbar, 0);

    // xyz passthrough: bounce straight back out via TMA (region not reused below)
    if (t == 0) {
        bulk_s2g(out_xyz + (size_t)base * 3, smem_u32(s_xyz), 768 * 4, pol);
    }

    // ---------------- compute ----------------
    float r, g, b, c00, c01, c02, c11, c12, c22;
    {
        float dx = s_vd[t * 3 + 0];
        float dy = s_vd[t * 3 + 1];
        float dz = s_vd[t * 3 + 2];
        const float4* sh4 = reinterpret_cast<const float4*>(s_sh);
        float4 shr = sh4[t * 3 + 0];
        float4 shg = sh4[t * 3 + 1];
        float4 shb = sh4[t * 3 + 2];
        r = sigmoidf_(C0 * shr.x - C1 * dy * shr.y + C1 * dz * shr.z - C1 * dx * shr.w);
        g = sigmoidf_(C0 * shg.x - C1 * dy * shg.y + C1 * dz * shg.z - C1 * dx * shg.w);
        b = sigmoidf_(C0 * shb.x - C1 * dy * shb.y + C1 * dz * shb.z - C1 * dx * shb.w);
    }
    {
        float s0 = __expf(s_sl[t * 3 + 0]);
        float s1 = __expf(s_sl[t * 3 + 1]);
        float s2 = __expf(s_sl[t * 3 + 2]);
        float inv = rsqrtf(fmaxf(q.x * q.x + q.y * q.y + q.z * q.z + q.w * q.w, 1e-24f));
        float qr = q.x * inv, qx = q.y * inv, qy = q.z * inv, qz = q.w * inv;

        float M00 = (1.0f - 2.0f * (qy * qy + qz * qz)) * s0;
        float M01 = (2.0f * (qx * qy - qr * qz)) * s1;
        float M02 = (2.0f * (qx * qz + qr * qy)) * s2;
        float M10 = (2.0f * (qx * qy + qr * qz)) * s0;
        float M11 = (1.0f - 2.0f * (qx * qx + qz * qz)) * s1;
        float M12 = (2.0f * (qy * qz - qr * qx)) * s2;
        float M20 = (2.0f * (qx * qz - qr * qy)) * s0;
        float M21 = (2.0f * (qy * qz + qr * qx)) * s1;
        float M22 = (1.0f - 2.0f * (qx * qx + qy * qy)) * s2;

        c00 = M00 * M00 + M01 * M01 + M02 * M02;
        c01 = M00 * M10 + M01 * M11 + M02 * M12;
        c02 = M00 * M20 + M01 * M21 + M02 * M22;
        c11 = M10 * M10 + M11 * M11 + M12 * M12;
        c12 = M10 * M20 + M11 * M21 + M12 * M22;
        c22 = M20 * M20 + M21 * M21 + M22 * M22;
    }
    __syncthreads();   // all input staging consumed

    // ---------------- stage outputs, TMA store ----------------
    float* s_cov = s + 768;    // 2304 floats
    float* s_rgb = s + 3072;   // 768 floats
    {
        float* cv = s_cov + t * 9;
        cv[0] = c00; cv[1] = c01; cv[2] = c02;
        cv[3] = c01; cv[4] = c11; cv[5] = c12;
        cv[6] = c02; cv[7] = c12; cv[8] = c22;
        s_rgb[t * 3 + 0] = r;
        s_rgb[t * 3 + 1] = g;
        s_rgb[t * 3 + 2] = b;
    }
    __syncthreads();

    if (t == 0) {
        asm volatile("fence.proxy.async.shared::cta;" ::: "memory");
        bulk_s2g(out_cov + (size_t)base * 9, smem_u32(s_cov), 2304 * 4, pol);
        bulk_s2g(out_rgb + (size_t)base * 3, smem_u32(s_rgb), 768 * 4, pol);
        asm volatile("cp.async.bulk.commit_group;" ::: "memory");
        asm volatile("cp.async.bulk.wait_group.read 0;" ::: "memory");
    }
}

extern "C" void kernel_launch(void* const* d_in, const int* in_sizes, int n_in,
                              void* d_out, int out_size) {
    const float* view_dirs     = (const float*)d_in[0];
    const float* xyz           = (const float*)d_in[1];
    const float* scale_log     = (const float*)d_in[2];
    const float* rot_quat      = (const float*)d_in[3];
    const float* opacity_logit = (const float*)d_in[4];
    const float* sh_coeffs     = (const float*)d_in[5];
    float* out = (float*)d_out;

    int n = in_sizes[1] / 3;
    int aligned = ((n & 3) == 0);   // output segment bases 16B-aligned

    int blocks = (n + 255) / 256;
    gaussian_kernel<<<blocks, 256>>>(view_dirs, xyz, scale_log, rot_quat,
                                     opacity_logit, sh_coeffs, out, n, aligned);
}